// round 10
// baseline (speedup 1.0000x reference)
#include <cuda_runtime.h>
#include <math.h>

// Problem constants
#define Nn 8
#define Cc 8
#define Tt 600
#define Ff 257
#define NCHUNK 12
#define TCHUNK 50               // Tt / NCHUNK
#define LOADC 7.0710678118654754e-04f   // 0.001/sqrt(2)

// Scratch (device globals — no allocation allowed in kernel_launch)
// g_phi: partial covariances [chunk][n][j][f], j = 0..71 (36 complex, upper tri, re/im interleaved)
__device__ float g_phi[(size_t)NCHUNK * Nn * 72 * Ff];
// g_phired: reduced covariance [n][j][f]
__device__ float g_phired[(size_t)Nn * 72 * Ff];
// g_w: conj(w) stored as [n][2c(+1)][f]
__device__ float g_w[(size_t)Nn * 16 * Ff];

// ---------------------------------------------------------------------------
// Kernel 1: partial noise covariance. phi[c][d] = sum_t v_c * conj(v_d), c<=d.
// Threads over f (coalesced). Grid: (f_tiles=3, chunk=12, n=8).
// ---------------------------------------------------------------------------
__global__ void __launch_bounds__(128) cov_kernel(const float* __restrict__ noise) {
    int f = blockIdx.x * 128 + threadIdx.x;
    if (f >= Ff) return;
    int chunk = blockIdx.y;
    int n = blockIdx.z;

    const size_t TF = (size_t)Tt * Ff;
    // noise[n][ri][c][t][f]
    const float* vr = noise + (size_t)n * 2 * Cc * TF + (size_t)(chunk * TCHUNK) * Ff + f;
    const float* vi = vr + Cc * TF;

    float acc[72];
#pragma unroll
    for (int j = 0; j < 72; j++) acc[j] = 0.f;

#pragma unroll 2
    for (int t = 0; t < TCHUNK; t++) {
        float yr[8], yi[8];
#pragma unroll
        for (int c = 0; c < 8; c++) {
            yr[c] = vr[c * TF + (size_t)t * Ff];
            yi[c] = vi[c * TF + (size_t)t * Ff];
        }
        int p = 0;
#pragma unroll
        for (int c = 0; c < 8; c++) {
#pragma unroll
            for (int d = c; d < 8; d++) {
                // v_c * conj(v_d)
                acc[2 * p]     += yr[c] * yr[d] + yi[c] * yi[d];
                acc[2 * p + 1] += yi[c] * yr[d] - yr[c] * yi[d];
                p++;
            }
        }
    }

    float* out = g_phi + ((size_t)(chunk * Nn + n) * 72) * Ff + f;
#pragma unroll
    for (int j = 0; j < 72; j++) out[(size_t)j * Ff] = acc[j];
}

// ---------------------------------------------------------------------------
// Kernel 2: reduce the 12 chunk partials. 148K threads, pure BW.
// ---------------------------------------------------------------------------
__global__ void __launch_bounds__(256) reduce_kernel() {
    int idx = blockIdx.x * 256 + threadIdx.x;     // over Nn*72*Ff
    const int total = Nn * 72 * Ff;
    if (idx >= total) return;
    float s = 0.f;
#pragma unroll
    for (int ch = 0; ch < NCHUNK; ch++)
        s += g_phi[(size_t)ch * total + idx];
    g_phired[idx] = s;
}

// ---------------------------------------------------------------------------
// Kernel 3: per-(n,f) 8x8 complex solve  phi x = d,  w = x / (d^H x).
// phi = 2*I + O(0.08) off-diagonal (diagonally dominant) -> unpivoted GE,
// fully unrolled so the matrix lives in registers.
// Stores conj(w) for the beamform pass.
// ---------------------------------------------------------------------------
struct C2 { float r, i; };
__device__ __forceinline__ C2 cmul(C2 a, C2 b) { return C2{a.r * b.r - a.i * b.i, a.r * b.i + a.i * b.r}; }
__device__ __forceinline__ C2 csub(C2 a, C2 b) { return C2{a.r - b.r, a.i - b.i}; }
__device__ __forceinline__ C2 cinv(C2 a) {
    float s = __frcp_rn(a.r * a.r + a.i * a.i);
    return C2{a.r * s, -a.i * s};
}

__global__ void __launch_bounds__(128) solve_kernel(const float* __restrict__ sv) {
    int idx = blockIdx.x * 128 + threadIdx.x;
    if (idx >= Nn * Ff) return;
    int n = idx / Ff;
    int f = idx - n * Ff;

    const float invT = 1.0f / (float)Tt;

    // Build augmented matrix A[8][9] (col 8 = steering vector d)
    C2 A[8][9];
    {
        const float* src = g_phired + ((size_t)n * 72) * Ff + f;
        int p = 0;
#pragma unroll
        for (int c = 0; c < 8; c++) {
#pragma unroll
            for (int d = c; d < 8; d++) {
                float re = src[(size_t)(2 * p) * Ff] * invT;
                float im = src[(size_t)(2 * p + 1) * Ff] * invT;
                if (c == d) {
                    A[c][c] = C2{re + LOADC, im + LOADC};   // complex diagonal loading
                } else {
                    A[c][d] = C2{re, im};
                    A[d][c] = C2{re, -im};                  // Hermitian
                }
                p++;
            }
        }
    }

    // steering vector: sv[n][ri][f][c]
    C2 dv[8];
    {
        const float* dr = sv + ((size_t)n * 2 * Ff + f) * Cc;
        const float* di = dr + (size_t)Ff * Cc;
#pragma unroll
        for (int c = 0; c < 8; c++) {
            dv[c] = C2{dr[c], di[c]};
            A[c][8] = dv[c];
        }
    }

    // Unpivoted Gaussian elimination (fully unrolled)
#pragma unroll
    for (int k = 0; k < 8; k++) {
        C2 pinv = cinv(A[k][k]);
#pragma unroll
        for (int r = 0; r < 8; r++) {
            if (r > k) {
                C2 fac = cmul(A[r][k], pinv);
#pragma unroll
                for (int col = 0; col < 9; col++) {
                    if (col > k) A[r][col] = csub(A[r][col], cmul(fac, A[k][col]));
                }
            }
        }
    }

    // Back substitution
    C2 x[8];
#pragma unroll
    for (int kk = 7; kk >= 0; kk--) {
        C2 s = A[kk][8];
#pragma unroll
        for (int col = 0; col < 8; col++) {
            if (col > kk) s = csub(s, cmul(A[kk][col], x[col]));
        }
        x[kk] = cmul(s, cinv(A[kk][kk]));
    }

    // denominator d^H x  (conj(d) . x)
    C2 deno = C2{0.f, 0.f};
#pragma unroll
    for (int c = 0; c < 8; c++) {
        deno.r += dv[c].r * x[c].r + dv[c].i * x[c].i;
        deno.i += dv[c].r * x[c].i - dv[c].i * x[c].r;
    }
    C2 dinv = cinv(deno);

    float* wout = g_w + (size_t)n * 16 * Ff + f;
#pragma unroll
    for (int c = 0; c < 8; c++) {
        C2 w = cmul(x[c], dinv);
        wout[(size_t)(2 * c) * Ff]     = w.r;      // store conj(w)
        wout[(size_t)(2 * c + 1) * Ff] = -w.i;
    }
}

// ---------------------------------------------------------------------------
// Kernel 4: beamform.  X[n,t,f] = sum_c conj(w[n,f,c]) * y[n,c,t,f]
// ---------------------------------------------------------------------------
__global__ void __launch_bounds__(256) bf_kernel(const float* __restrict__ mix,
                                                 float* __restrict__ out) {
    int idx = blockIdx.x * 256 + threadIdx.x;
    const int total = Nn * Tt * Ff;
    if (idx >= total) return;
    int f = idx % Ff;
    int nt = idx / Ff;
    int t = nt % Tt;
    int n = nt / Tt;

    const size_t TF = (size_t)Tt * Ff;
    const float* yr = mix + (size_t)n * 2 * Cc * TF + (size_t)t * Ff + f;
    const float* yi = yr + Cc * TF;
    const float* w = g_w + (size_t)n * 16 * Ff + f;   // conj(w): (ar, ai)

    float Xr = 0.f, Xi = 0.f;
#pragma unroll
    for (int c = 0; c < 8; c++) {
        float ar = w[(size_t)(2 * c) * Ff];
        float ai = w[(size_t)(2 * c + 1) * Ff];
        float r = yr[c * TF];
        float im = yi[c * TF];
        Xr += ar * r - ai * im;
        Xi += ar * im + ai * r;
    }

    // out[n][ri][0][t][f]
    float* o = out + (size_t)n * 2 * TF + (size_t)t * Ff + f;
    o[0]  = Xr;
    o[TF] = Xi;
}

// ---------------------------------------------------------------------------
extern "C" void kernel_launch(void* const* d_in, const int* in_sizes, int n_in,
                              void* d_out, int out_size) {
    const float* mixture = (const float*)d_in[0];
    const float* noise   = (const float*)d_in[1];
    const float* sv      = (const float*)d_in[2];
    float* out = (float*)d_out;

    // 1. partial covariance over noise
    dim3 g1((Ff + 127) / 128, NCHUNK, Nn);
    cov_kernel<<<g1, 128>>>(noise);

    // 2. reduce chunk partials
    int rtotal = Nn * 72 * Ff;
    reduce_kernel<<<(rtotal + 255) / 256, 256>>>();

    // 3. per-(n,f) solve + weight
    int stotal = Nn * Ff;
    solve_kernel<<<(stotal + 127) / 128, 128>>>(sv);

    // 4. beamform
    int btotal = Nn * Tt * Ff;
    bf_kernel<<<(btotal + 255) / 256, 256>>>(mixture, out);
}

// round 11
// speedup vs baseline: 1.1150x; 1.1150x over previous
#include <cuda_runtime.h>
#include <math.h>

// Problem constants
#define Nn 8
#define Cc 8
#define Tt 600
#define Ff 257
#define NCHUNK 24
#define TCHUNK 25               // Tt / NCHUNK
#define LOADC 7.0710678118654754e-04f   // 0.001/sqrt(2)
#define TB 8                    // t-values per bf thread
#define NTC (Tt / TB)           // 75

// Scratch (device globals — no allocation allowed)
__device__ __align__(16) float g_phi[(size_t)NCHUNK * Nn * 72 * Ff];
__device__ __align__(16) float g_phired[(size_t)Nn * 72 * Ff];
__device__ __align__(16) float g_w[(size_t)Nn * 16 * Ff];

// ---------------------------------------------------------------------------
// Kernel 1: partial noise covariance. phi[c][d] = sum_t v_c * conj(v_d), c<=d.
// Threads over f (coalesced). Grid: (3, NCHUNK, Nn) x 128.
// ---------------------------------------------------------------------------
__global__ void __launch_bounds__(128) cov_kernel(const float* __restrict__ noise) {
    int f = blockIdx.x * 128 + threadIdx.x;
    if (f >= Ff) return;
    int chunk = blockIdx.y;
    int n = blockIdx.z;

    const size_t TF = (size_t)Tt * Ff;
    const float* vr = noise + (size_t)n * 2 * Cc * TF + (size_t)(chunk * TCHUNK) * Ff + f;
    const float* vi = vr + Cc * TF;

    float acc[72];
#pragma unroll
    for (int j = 0; j < 72; j++) acc[j] = 0.f;

#pragma unroll 2
    for (int t = 0; t < TCHUNK; t++) {
        float yr[8], yi[8];
#pragma unroll
        for (int c = 0; c < 8; c++) {
            yr[c] = vr[c * TF + (size_t)t * Ff];
            yi[c] = vi[c * TF + (size_t)t * Ff];
        }
        int p = 0;
#pragma unroll
        for (int c = 0; c < 8; c++) {
#pragma unroll
            for (int d = c; d < 8; d++) {
                acc[2 * p]     += yr[c] * yr[d] + yi[c] * yi[d];
                acc[2 * p + 1] += yi[c] * yr[d] - yr[c] * yi[d];
                p++;
            }
        }
    }

    float* out = g_phi + ((size_t)(chunk * Nn + n) * 72) * Ff + f;
#pragma unroll
    for (int j = 0; j < 72; j++) out[(size_t)j * Ff] = acc[j];
}

// ---------------------------------------------------------------------------
// Kernel 2: fold NCHUNK partials, float4-vectorized.
// total = Nn*72*Ff = 148032 floats = 37008 float4.
// ---------------------------------------------------------------------------
__global__ void __launch_bounds__(256) reduce_kernel() {
    const int total4 = (Nn * 72 * Ff) / 4;          // 37008
    int idx = blockIdx.x * 256 + threadIdx.x;
    if (idx >= total4) return;
    const float4* src = (const float4*)g_phi;
    float4 s = src[idx];
#pragma unroll
    for (int ch = 1; ch < NCHUNK; ch++) {
        float4 v = src[(size_t)ch * total4 + idx];
        s.x += v.x; s.y += v.y; s.z += v.z; s.w += v.w;
    }
    ((float4*)g_phired)[idx] = s;
}

// ---------------------------------------------------------------------------
// Kernel 3: warp-cooperative 8x8 complex solve, 8 lanes per (n,f) problem,
// one matrix row per lane (18 floats — no spills). Pivot rows broadcast via
// width-8 shuffles. phi is diagonally dominant (diag ~2, off-diag ~0.08) so
// unpivoted elimination is numerically safe.
// ---------------------------------------------------------------------------
struct C2 { float r, i; };
__device__ __forceinline__ C2 cmul(C2 a, C2 b) { return C2{a.r * b.r - a.i * b.i, a.r * b.i + a.i * b.r}; }
__device__ __forceinline__ C2 csub(C2 a, C2 b) { return C2{a.r - b.r, a.i - b.i}; }
__device__ __forceinline__ C2 cinv(C2 a) {
    float s = __frcp_rn(a.r * a.r + a.i * a.i);
    return C2{a.r * s, -a.i * s};
}
__device__ __forceinline__ C2 bcast8(unsigned mask, C2 v, int src) {
    return C2{__shfl_sync(mask, v.r, src, 8), __shfl_sync(mask, v.i, src, 8)};
}

__global__ void __launch_bounds__(256) solve_kernel(const float* __restrict__ sv) {
    int gid = blockIdx.x * 256 + threadIdx.x;
    int r = gid & 7;                 // my matrix row
    int prob = gid >> 3;             // (n,f) problem index
    if (prob >= Nn * Ff) prob = Nn * Ff - 1;   // clamp: dup groups write same values
    int n = prob / Ff;
    int f = prob - n * Ff;
    const unsigned mask = 0xFFFFFFFFu;

    const float invT = 1.0f / (float)Tt;
    const float* src = g_phired + (size_t)n * 72 * Ff + f;

    // Build my row of the augmented system [phi | d]
    C2 row[9];
#pragma unroll
    for (int c = 0; c < 8; c++) {
        int a = (r < c) ? r : c;
        int b = (r < c) ? c : r;
        int p = a * 8 - a * (a - 1) / 2 + (b - a);    // upper-tri index
        float re = src[(size_t)(2 * p) * Ff] * invT;
        float im = src[(size_t)(2 * p + 1) * Ff] * invT;
        if (c < r) im = -im;                          // Hermitian conj
        if (c == r) { re += LOADC; im += LOADC; }     // complex diag loading
        row[c] = C2{re, im};
    }
    // steering vector: sv[n][ri][f][c]
    const float* dr = sv + ((size_t)n * 2 * Ff + f) * Cc;
    C2 dn = C2{dr[r], dr[(size_t)Ff * Cc + r]};
    row[8] = dn;

    // Forward elimination (unpivoted), pivot row broadcast from lane k
#pragma unroll
    for (int k = 0; k < 8; k++) {
        C2 piv = bcast8(mask, row[k], k);
        C2 fac = cmul(row[k], cinv(piv));
#pragma unroll
        for (int col = k + 1; col < 9; col++) {
            C2 pk = bcast8(mask, row[col], k);
            if (r > k) row[col] = csub(row[col], cmul(fac, pk));
        }
    }

    // Back substitution: x[k] broadcast as soon as computed
    C2 s = row[8];
    C2 myx = C2{0.f, 0.f};
#pragma unroll
    for (int k = 7; k >= 0; k--) {
        C2 sk = bcast8(mask, s, k);
        C2 dk = bcast8(mask, row[k], k);
        C2 xk = cmul(sk, cinv(dk));
        if (r == k) myx = xk;
        if (r < k) s = csub(s, cmul(row[k], xk));
    }

    // deno = d^H x, reduced across the 8 lanes
    C2 term = C2{dn.r * myx.r + dn.i * myx.i, dn.r * myx.i - dn.i * myx.r};
#pragma unroll
    for (int off = 4; off; off >>= 1) {
        term.r += __shfl_xor_sync(mask, term.r, off, 8);
        term.i += __shfl_xor_sync(mask, term.i, off, 8);
    }
    C2 w = cmul(myx, cinv(term));

    // store conj(w) in [n][2c][f] layout
    float* wout = g_w + (size_t)n * 16 * Ff + f;
    wout[(size_t)(2 * r) * Ff]     = w.r;
    wout[(size_t)(2 * r + 1) * Ff] = -w.i;
}

// ---------------------------------------------------------------------------
// Kernel 4: beamform with per-thread t-loop (weights register-resident).
// f padded to 288 so warps never straddle a t-chunk boundary.
// ---------------------------------------------------------------------------
__global__ void __launch_bounds__(256) bf_kernel(const float* __restrict__ mix,
                                                 float* __restrict__ out) {
    const int FP = 288;
    int idx = blockIdx.x * 256 + threadIdx.x;
    int f = idx % FP;
    int rest = idx / FP;
    int tc = rest % NTC;
    int n = rest / NTC;
    if (f >= Ff || n >= Nn) return;

    const size_t TF = (size_t)Tt * Ff;

    // load my 8 complex weights once
    const float* w = g_w + (size_t)n * 16 * Ff + f;
    float wr[8], wi[8];
#pragma unroll
    for (int c = 0; c < 8; c++) {
        wr[c] = w[(size_t)(2 * c) * Ff];
        wi[c] = w[(size_t)(2 * c + 1) * Ff];
    }

    const float* base = mix + (size_t)n * 2 * Cc * TF + (size_t)(tc * TB) * Ff + f;
    float* o = out + (size_t)n * 2 * TF + (size_t)(tc * TB) * Ff + f;

#pragma unroll
    for (int t = 0; t < TB; t++) {
        float Xr = 0.f, Xi = 0.f;
#pragma unroll
        for (int c = 0; c < 8; c++) {
            float yr = base[c * TF + (size_t)t * Ff];
            float yi = base[Cc * TF + c * TF + (size_t)t * Ff];
            Xr += wr[c] * yr - wi[c] * yi;
            Xi += wr[c] * yi + wi[c] * yr;
        }
        o[(size_t)t * Ff]      = Xr;
        o[TF + (size_t)t * Ff] = Xi;
    }
}

// ---------------------------------------------------------------------------
extern "C" void kernel_launch(void* const* d_in, const int* in_sizes, int n_in,
                              void* d_out, int out_size) {
    const float* mixture = (const float*)d_in[0];
    const float* noise   = (const float*)d_in[1];
    const float* sv      = (const float*)d_in[2];
    float* out = (float*)d_out;

    // 1. partial covariance over noise
    dim3 g1((Ff + 127) / 128, NCHUNK, Nn);
    cov_kernel<<<g1, 128>>>(noise);

    // 2. reduce chunk partials (float4)
    int rtotal4 = (Nn * 72 * Ff) / 4;
    reduce_kernel<<<(rtotal4 + 255) / 256, 256>>>();

    // 3. warp-cooperative solve: 8 lanes per (n,f)
    int sthreads = Nn * Ff * 8;
    solve_kernel<<<(sthreads + 255) / 256, 256>>>(sv);

    // 4. beamform
    int bthreads = Nn * NTC * 288;
    bf_kernel<<<(bthreads + 255) / 256, 256>>>(mixture, out);
}